// round 5
// baseline (speedup 1.0000x reference)
#include <cuda_runtime.h>
#include <cuda_bf16.h>
#include <cstdint>
#include <cstddef>

#define Hdim 1024
#define Edim 18432
#define Vdim 32000
#define Tlen 15

struct State {
    float feat[Hdim];
    float h[Hdim], c[Hdim];
    float tmph[Hdim], tmpc[Hdim];
    float h1[Hdim], c1[Hdim];
    float h2[2][Hdim], c2[2][Hdim];
    float h3[2][Hdim], c3[2][Hdim];
    float word[Hdim];
    float hi[Vdim];
    unsigned long long lomax;
    unsigned ticket1, ticket2;
};
__device__ State g_s;
__device__ unsigned g_fcw[(size_t)Vdim * (Hdim / 2)];   // bf16x2-packed fc_w (65.5 MB)

// ---------- helpers ----------
__device__ __forceinline__ float sigf(float x) { return 1.0f / (1.0f + expf(-x)); }

__device__ __forceinline__ float warp_sum(float s) {
#pragma unroll
    for (int o = 16; o; o >>= 1) s += __shfl_xor_sync(0xffffffffu, s, o);
    return s;
}

// block reduce across 256 threads (8 warps)
__device__ __forceinline__ float block_sum(float s) {
    __shared__ float sm[8];
    __shared__ float outv;
    int w = threadIdx.x >> 5, lane = threadIdx.x & 31;
    s = warp_sum(s);
    if (lane == 0) sm[w] = s;
    __syncthreads();
    if (w == 0) {
        float r = (lane < 8) ? sm[lane] : 0.0f;
        r = warp_sum(r);
        if (lane == 0) outv = r;
    }
    __syncthreads();
    float res = outv;
    __syncthreads();
    return res;
}

__device__ __forceinline__ unsigned long long packkey(float v, unsigned idx) {
    unsigned u = __float_as_uint(v);
    u = (u & 0x80000000u) ? ~u : (u | 0x80000000u);
    return ((unsigned long long)u << 32) | (unsigned long long)(0xFFFFFFFFu - idx);
}
__device__ __forceinline__ float key_val(unsigned long long k) {
    unsigned u = (unsigned)(k >> 32);
    u = (u & 0x80000000u) ? (u ^ 0x80000000u) : ~u;
    return __uint_as_float(u);
}
__device__ __forceinline__ int key_idx(unsigned long long k) {
    return (int)(0xFFFFFFFFu - (unsigned)(k & 0xFFFFFFFFull));
}

// ---------- LayerNorm by one 256-thread block ----------
__device__ void ln256(const float* __restrict__ x, const float* __restrict__ g,
                      const float* __restrict__ b, const float* __restrict__ base,
                      float* __restrict__ o) {
    float xv[4];
    float s = 0.f;
#pragma unroll
    for (int k = 0; k < 4; k++) { xv[k] = x[threadIdx.x + 256 * k]; s += xv[k]; }
    float m = block_sum(s) * (1.f / Hdim);
    float q = 0.f;
#pragma unroll
    for (int k = 0; k < 4; k++) { float d = xv[k] - m; q += d * d; }
    float v = block_sum(q) * (1.f / Hdim);
    float inv = rsqrtf(v + 1e-5f);
#pragma unroll
    for (int k = 0; k < 4; k++) {
        int i = threadIdx.x + 256 * k;
        float r = (xv[k] - m) * inv * g[i] + b[i];
        if (base) r += base[i];
        o[i] = r;
    }
}

// ---------- prologue: fc1 rows (blocks < Hdim) + bf16 convert (rest) ----------
__global__ void __launch_bounds__(256) k_pro1(
    const float* __restrict__ feats, const float* __restrict__ w,
    const float* __restrict__ bias, const float* __restrict__ fcw32) {
    if (blockIdx.x < Hdim) {
        int j = blockIdx.x;
        const float4* Wr = (const float4*)(w + (size_t)j * Edim);
        const float4* X  = (const float4*)feats;
        float s = 0.f;
        for (int i = threadIdx.x; i < Edim / 4; i += 256) {
            float4 a = __ldcs(&Wr[i]), v = X[i];
            s += a.x * v.x + a.y * v.y + a.z * v.z + a.w * v.w;
        }
        s = block_sum(s);
        if (threadIdx.x == 0) g_s.feat[j] = fmaxf(s + bias[j], 0.f);
    } else {
        const float4* src = (const float4*)fcw32;
        uint2* dst = (uint2*)g_fcw;
        const int total = Vdim * (Hdim / 4);
        int start  = (blockIdx.x - Hdim) * 256 + threadIdx.x;
        int stride = (gridDim.x - Hdim) * 256;
        for (int i = start; i < total; i += stride) {
            float4 f = __ldcs(&src[i]);
            uint2 u;
            u.x = (unsigned)__bfloat16_as_ushort(__float2bfloat16(f.x))
                | ((unsigned)__bfloat16_as_ushort(__float2bfloat16(f.y)) << 16);
            u.y = (unsigned)__bfloat16_as_ushort(__float2bfloat16(f.z))
                | ((unsigned)__bfloat16_as_ushort(__float2bfloat16(f.w)) << 16);
            dst[i] = u;
        }
    }
}

// ---------- init h/c GEMVs + (last block) prologue LayerNorms ----------
__global__ void __launch_bounds__(256) k_init2(
    const float* __restrict__ wh, const float* __restrict__ bh,
    const float* __restrict__ wc, const float* __restrict__ bc,
    const float* __restrict__ lnhg, const float* __restrict__ lnhb,
    const float* __restrict__ lncg, const float* __restrict__ lncb) {
    int j = blockIdx.x;
    bool ish = j < Hdim;
    int r = ish ? j : j - Hdim;
    const float4* Wr = (const float4*)((ish ? wh : wc) + (size_t)r * Hdim);
    const float4* X  = (const float4*)g_s.feat;
    float4 a = __ldcs(&Wr[threadIdx.x]), v = X[threadIdx.x];
    float s = a.x * v.x + a.y * v.y + a.z * v.z + a.w * v.w;
    s = block_sum(s);
    __shared__ bool lastb;
    if (threadIdx.x == 0) {
        float val = fmaxf(s + (ish ? bh[r] : bc[r]), 0.f);
        if (ish) g_s.tmph[r] = val; else g_s.tmpc[r] = val;
        __threadfence();
        lastb = (atomicAdd(&g_s.ticket1, 1u) == 2u * Hdim - 1u);
    }
    __syncthreads();
    if (!lastb) return;
    ln256(g_s.tmph, lnhg, lnhb, nullptr, g_s.h);
    ln256(g_s.tmpc, lncg, lncb, nullptr, g_s.c);
    if (threadIdx.x == 0) g_s.ticket1 = 0;
}

// ---------- LSTM cell: 512 blocks, each warp does 2 adjacent rows of one gate ----------
// warps 0-3: W_ih gates i,f,g,o ; warps 4-7: W_hh gates. 16 weight float4s in flight/thread.
// FUSELN: blocks >= Hdim/2 do the LayerNorms for the next step.
template <bool FUSELN>
__global__ void __launch_bounds__(256) k_cell(
    const float* __restrict__ x, const float* __restrict__ hin, const float* __restrict__ cin,
    const float* __restrict__ wih, const float* __restrict__ whh,
    const float* __restrict__ bih, const float* __restrict__ bhh,
    float* __restrict__ hout, float* __restrict__ cout,
    const float* __restrict__ lnhg, const float* __restrict__ lnhb,
    const float* __restrict__ lncg, const float* __restrict__ lncb) {
    if (FUSELN && blockIdx.x >= Hdim / 2) {
        bool ish = (blockIdx.x == Hdim / 2);
        ln256(ish ? g_s.h1 : g_s.c1,
              ish ? lnhg : lncg, ish ? lnhb : lncb,
              ish ? g_s.h : g_s.c,
              ish ? g_s.tmph : g_s.tmpc);
        return;
    }
    int j0 = blockIdx.x * 2;
    int w = threadIdx.x >> 5, lane = threadIdx.x & 31;
    int g = w & 3;
    const float* Wm  = (w < 4) ? wih : whh;
    const float* vec = (w < 4) ? x : hin;
    const float4* WrA = (const float4*)(Wm + ((size_t)g * Hdim + j0) * Hdim);
    const float4* WrB = WrA + (Hdim / 4);
    const float4* v4  = (const float4*)vec;
    float s0 = 0.f, s1 = 0.f;
#pragma unroll
    for (int i = 0; i < 8; i++) {
        int q = lane + 32 * i;
        float4 b  = v4[q];
        float4 a0 = WrA[q];
        float4 a1 = WrB[q];
        s0 += a0.x * b.x + a0.y * b.y + a0.z * b.z + a0.w * b.w;
        s1 += a1.x * b.x + a1.y * b.y + a1.z * b.z + a1.w * b.w;
    }
    s0 = warp_sum(s0);
    s1 = warp_sum(s1);
    __shared__ float red[2][8];
    if (lane == 0) { red[0][w] = s0; red[1][w] = s1; }
    __syncthreads();
    if (threadIdx.x == 0 || threadIdx.x == 32) {
        int rr = threadIdx.x >> 5;        // 0 or 1
        int j = j0 + rr;
        float gi = red[rr][0] + red[rr][4] + bih[j]            + bhh[j];
        float gf = red[rr][1] + red[rr][5] + bih[j + Hdim]     + bhh[j + Hdim];
        float gg = red[rr][2] + red[rr][6] + bih[j + 2 * Hdim] + bhh[j + 2 * Hdim];
        float go = red[rr][3] + red[rr][7] + bih[j + 3 * Hdim] + bhh[j + 3 * Hdim];
        float cn = sigf(gf) * cin[j] + sigf(gi) * tanhf(gg);
        cout[j] = cn;
        hout[j] = sigf(go) * tanhf(cn);
    }
}

// ---------- vocab GEMV (bf16) + interval bound + (last block) exact refine & emit ----------
__global__ void __launch_bounds__(256) k_fcb(
    const float* __restrict__ x, const float* __restrict__ fcb,
    const float* __restrict__ fcw32, const float* __restrict__ embed,
    const float* __restrict__ tot, float* __restrict__ out, int t) {
    int tid = threadIdx.x, wid = tid >> 5, lane = tid & 31;
    const float4* X = (const float4*)x;
    float4 xc[8];
#pragma unroll
    for (int k = 0; k < 4; k++) {
        int q = lane + 32 * k;
        xc[2 * k]     = X[2 * q];
        xc[2 * k + 1] = X[2 * q + 1];
    }
    unsigned long long wbest = 0ull;
    int r0 = (blockIdx.x * 8 + wid) * 4;
#pragma unroll
    for (int rr = 0; rr < 4; rr++) {
        int r = r0 + rr;
        const uint4* W = (const uint4*)(g_fcw + (size_t)r * (Hdim / 2));
        float v = 0.f, a = 0.f;
#pragma unroll
        for (int k = 0; k < 4; k++) {
            uint4 w4 = W[lane + 32 * k];
            float4 xA = xc[2 * k], xB = xc[2 * k + 1];
            float p0 = __uint_as_float(w4.x << 16)         * xA.x;
            float p1 = __uint_as_float(w4.x & 0xffff0000u) * xA.y;
            float p2 = __uint_as_float(w4.y << 16)         * xA.z;
            float p3 = __uint_as_float(w4.y & 0xffff0000u) * xA.w;
            float p4 = __uint_as_float(w4.z << 16)         * xB.x;
            float p5 = __uint_as_float(w4.z & 0xffff0000u) * xB.y;
            float p6 = __uint_as_float(w4.w << 16)         * xB.z;
            float p7 = __uint_as_float(w4.w & 0xffff0000u) * xB.w;
            v += p0 + p1 + p2 + p3 + p4 + p5 + p6 + p7;
            a += fabsf(p0) + fabsf(p1) + fabsf(p2) + fabsf(p3)
               + fabsf(p4) + fabsf(p5) + fabsf(p6) + fabsf(p7);
        }
        v = warp_sum(v);
        a = warp_sum(a);
        if (lane == 0) {
            v += fcb[r];
            float err = a * 0.0042f + 1e-6f;
            g_s.hi[r] = v + err;
            unsigned long long key = packkey(v - err, (unsigned)r);
            if (key > wbest) wbest = key;
        }
    }
    __shared__ unsigned long long sb[8];
    __shared__ bool lastb;
    if (lane == 0) sb[wid] = wbest;
    __syncthreads();
    if (tid == 0) {
        unsigned long long m = sb[0];
#pragma unroll
        for (int k = 1; k < 8; k++) if (sb[k] > m) m = sb[k];
        atomicMax(&g_s.lomax, m);
        __threadfence();
        lastb = (atomicAdd(&g_s.ticket2, 1u) == gridDim.x - 1u);
    }
    __syncthreads();
    if (!lastb) return;

    // ------- finish (sole surviving block; all hi/lomax writes fenced-visible) -------
    // Warp-ballot scan of hi[] + exact fp32 re-dot of every qualifying row. No truncation.
    __shared__ unsigned long long swr[8];
    __shared__ int s_idx;
    __shared__ float s_tok;
    float lo;
    {
        __shared__ unsigned long long s_lom;
        if (tid == 0) s_lom = atomicAdd(&g_s.lomax, 0ull);
        __syncthreads();
        lo = key_val(s_lom);
    }
    float4 x4c[8];
#pragma unroll
    for (int k = 0; k < 8; k++) x4c[k] = X[lane + 32 * k];
    unsigned long long rbest = 0ull;
    for (int rb = wid * 32; rb < Vdim; rb += 256) {
        bool qual = (g_s.hi[rb + lane] >= lo);
        unsigned m = __ballot_sync(0xffffffffu, qual);
        while (m) {
            int b = __ffs(m) - 1;
            m &= m - 1;
            int row = rb + b;
            const float4* Wr = (const float4*)(fcw32 + (size_t)row * Hdim);
            float d = 0.f;
#pragma unroll
            for (int k = 0; k < 8; k++) {
                float4 a = Wr[lane + 32 * k];
                d += a.x * x4c[k].x + a.y * x4c[k].y + a.z * x4c[k].z + a.w * x4c[k].w;
            }
            d = warp_sum(d);
            if (lane == 0) {
                unsigned long long key = packkey(d + fcb[row], (unsigned)row);
                if (key > rbest) rbest = key;
            }
        }
    }
    if (lane == 0) swr[wid] = rbest;
    __syncthreads();
    if (tid == 0) {
        unsigned long long m = swr[0];
#pragma unroll
        for (int k = 1; k < 8; k++) if (swr[k] > m) m = swr[k];
        s_idx = key_idx(m);
        s_tok = tot[s_idx];
        g_s.lomax = 0ull;
        g_s.ticket2 = 0u;
    }
    __syncthreads();
    int idx = s_idx;
    ((float4*)g_s.word)[tid] = ((const float4*)(embed + (size_t)idx * Hdim))[tid];
    out[tid * Tlen + t] = s_tok;   // batch == 256 == blockDim
}

extern "C" void kernel_launch(void* const* d_in, const int* in_sizes, int n_in,
                              void* d_out, int out_size) {
    const float* features  = (const float*)d_in[0];
    const float* fc1_w     = (const float*)d_in[1];
    const float* fc1_b     = (const float*)d_in[2];
    const float* init_h_w  = (const float*)d_in[3];
    const float* init_h_b  = (const float*)d_in[4];
    const float* init_c_w  = (const float*)d_in[5];
    const float* init_c_b  = (const float*)d_in[6];
    const float* ln_h_g    = (const float*)d_in[7];
    const float* ln_h_b    = (const float*)d_in[8];
    const float* ln_c_g    = (const float*)d_in[9];
    const float* ln_c_b    = (const float*)d_in[10];
    const float* w_ih1     = (const float*)d_in[11];
    const float* w_hh1     = (const float*)d_in[12];
    const float* b_ih1     = (const float*)d_in[13];
    const float* b_hh1     = (const float*)d_in[14];
    const float* w_ih2     = (const float*)d_in[15];
    const float* w_hh2     = (const float*)d_in[16];
    const float* b_ih2     = (const float*)d_in[17];
    const float* b_hh2     = (const float*)d_in[18];
    const float* fc_w      = (const float*)d_in[19];
    const float* fc_b      = (const float*)d_in[20];
    const float* embed_w   = (const float*)d_in[21];
    const float* totoken_w = (const float*)d_in[22];
    float* out = (float*)d_out;

    State* S = nullptr;
    cudaGetSymbolAddress((void**)&S, g_s);

    // prologue: feat GEMV + bf16 convert (one kernel), then init GEMVs + LN (one kernel)
    k_pro1<<<Hdim + 1480, 256>>>(features, fc1_w, fc1_b, fc_w);
    k_init2<<<2 * Hdim, 256>>>(init_h_w, init_h_b, init_c_w, init_c_b,
                               ln_h_g, ln_h_b, ln_c_g, ln_c_b);

    // ---- step 0 ----
    k_cell<false><<<Hdim / 2, 256>>>(S->feat, S->h, S->c,
        w_ih1, w_hh1, b_ih1, b_hh1, S->h1, S->c1,
        nullptr, nullptr, nullptr, nullptr);
    k_cell<true><<<Hdim / 2 + 2, 256>>>(S->h1, S->h, S->c,
        w_ih2, w_hh2, b_ih2, b_hh2, S->h2[0], S->c2[0],
        ln_h_g, ln_h_b, ln_c_g, ln_c_b);
    k_cell<false><<<Hdim / 2, 256>>>(S->h2[0], S->h, S->c,
        w_ih2, w_hh2, b_ih2, b_hh2, S->h3[0], S->c3[0],
        nullptr, nullptr, nullptr, nullptr);
    k_fcb<<<Vdim / 32, 256>>>(S->h3[0], fc_b, fc_w, embed_w, totoken_w, out, 0);

    // ---- steps 1..14 ----
    int p = 0;
    for (int t = 1; t < Tlen; t++) {
        int q = 1 - p;
        k_cell<false><<<Hdim / 2, 256>>>(S->word, S->tmph, S->tmpc,
            w_ih1, w_hh1, b_ih1, b_hh1, S->h1, S->c1,
            nullptr, nullptr, nullptr, nullptr);
        k_cell<true><<<Hdim / 2 + 2, 256>>>(S->h1, S->h2[p], S->c2[p],
            w_ih2, w_hh2, b_ih2, b_hh2, S->h2[q], S->c2[q],
            ln_h_g, ln_h_b, ln_c_g, ln_c_b);
        k_cell<false><<<Hdim / 2, 256>>>(S->h2[q], S->h3[p], S->c3[p],
            w_ih2, w_hh2, b_ih2, b_hh2, S->h3[q], S->c3[q],
            nullptr, nullptr, nullptr, nullptr);
        k_fcb<<<Vdim / 32, 256>>>(S->h3[q], fc_b, fc_w, embed_w, totoken_w, out, t);
        p = q;
    }
}

// round 6
// speedup vs baseline: 1.3248x; 1.3248x over previous
#include <cuda_runtime.h>
#include <cuda_bf16.h>
#include <cstdint>
#include <cstddef>

#define Hdim 1024
#define Edim 18432
#define Vdim 32000
#define Tlen 15

struct State {
    float feat[Hdim];
    float h[Hdim], c[Hdim];
    float tmph[Hdim], tmpc[Hdim];
    float h1[Hdim], c1[Hdim];
    float h2[2][Hdim], c2[2][Hdim];
    float h3[2][Hdim], c3[2][Hdim];
    float word[Hdim];
    float hi[Vdim];
    unsigned long long lomax;
    unsigned ticket1, ticket2;
};
__device__ State g_s;
__device__ unsigned g_fcw[(size_t)Vdim * (Hdim / 2)];   // bf16x2-packed fc_w (65.5 MB)

// ---------- helpers ----------
__device__ __forceinline__ float sigf(float x) { return 1.0f / (1.0f + expf(-x)); }

__device__ __forceinline__ float warp_sum(float s) {
#pragma unroll
    for (int o = 16; o; o >>= 1) s += __shfl_xor_sync(0xffffffffu, s, o);
    return s;
}

// block reduce across 256 threads (8 warps)
__device__ __forceinline__ float block_sum(float s) {
    __shared__ float sm[8];
    __shared__ float outv;
    int w = threadIdx.x >> 5, lane = threadIdx.x & 31;
    s = warp_sum(s);
    if (lane == 0) sm[w] = s;
    __syncthreads();
    if (w == 0) {
        float r = (lane < 8) ? sm[lane] : 0.0f;
        r = warp_sum(r);
        if (lane == 0) outv = r;
    }
    __syncthreads();
    float res = outv;
    __syncthreads();
    return res;
}

__device__ __forceinline__ unsigned long long packkey(float v, unsigned idx) {
    unsigned u = __float_as_uint(v);
    u = (u & 0x80000000u) ? ~u : (u | 0x80000000u);
    return ((unsigned long long)u << 32) | (unsigned long long)(0xFFFFFFFFu - idx);
}
__device__ __forceinline__ float key_val(unsigned long long k) {
    unsigned u = (unsigned)(k >> 32);
    u = (u & 0x80000000u) ? (u ^ 0x80000000u) : ~u;
    return __uint_as_float(u);
}
__device__ __forceinline__ int key_idx(unsigned long long k) {
    return (int)(0xFFFFFFFFu - (unsigned)(k & 0xFFFFFFFFull));
}

// ---------- LayerNorm by one 256-thread block ----------
__device__ void ln256(const float* __restrict__ x, const float* __restrict__ g,
                      const float* __restrict__ b, const float* __restrict__ base,
                      float* __restrict__ o) {
    float xv[4];
    float s = 0.f;
#pragma unroll
    for (int k = 0; k < 4; k++) { xv[k] = x[threadIdx.x + 256 * k]; s += xv[k]; }
    float m = block_sum(s) * (1.f / Hdim);
    float q = 0.f;
#pragma unroll
    for (int k = 0; k < 4; k++) { float d = xv[k] - m; q += d * d; }
    float v = block_sum(q) * (1.f / Hdim);
    float inv = rsqrtf(v + 1e-5f);
#pragma unroll
    for (int k = 0; k < 4; k++) {
        int i = threadIdx.x + 256 * k;
        float r = (xv[k] - m) * inv * g[i] + b[i];
        if (base) r += base[i];
        o[i] = r;
    }
}

// ---------- prologue: fc1 rows (blocks < Hdim) + bf16 convert (rest) ----------
__global__ void __launch_bounds__(256) k_pro1(
    const float* __restrict__ feats, const float* __restrict__ w,
    const float* __restrict__ bias, const float* __restrict__ fcw32) {
    if (blockIdx.x < Hdim) {
        int j = blockIdx.x;
        const float4* Wr = (const float4*)(w + (size_t)j * Edim);
        const float4* X  = (const float4*)feats;
        float s = 0.f;
        for (int i = threadIdx.x; i < Edim / 4; i += 256) {
            float4 a = __ldcs(&Wr[i]), v = X[i];
            s += a.x * v.x + a.y * v.y + a.z * v.z + a.w * v.w;
        }
        s = block_sum(s);
        if (threadIdx.x == 0) g_s.feat[j] = fmaxf(s + bias[j], 0.f);
    } else {
        const float4* src = (const float4*)fcw32;
        uint2* dst = (uint2*)g_fcw;
        const int total = Vdim * (Hdim / 4);
        int start  = (blockIdx.x - Hdim) * 256 + threadIdx.x;
        int stride = (gridDim.x - Hdim) * 256;
        for (int i = start; i < total; i += stride) {
            float4 f = __ldcs(&src[i]);
            uint2 u;
            u.x = (unsigned)__bfloat16_as_ushort(__float2bfloat16(f.x))
                | ((unsigned)__bfloat16_as_ushort(__float2bfloat16(f.y)) << 16);
            u.y = (unsigned)__bfloat16_as_ushort(__float2bfloat16(f.z))
                | ((unsigned)__bfloat16_as_ushort(__float2bfloat16(f.w)) << 16);
            dst[i] = u;
        }
    }
}

// ---------- init h/c GEMVs + (last block) prologue LayerNorms ----------
__global__ void __launch_bounds__(256) k_init2(
    const float* __restrict__ wh, const float* __restrict__ bh,
    const float* __restrict__ wc, const float* __restrict__ bc,
    const float* __restrict__ lnhg, const float* __restrict__ lnhb,
    const float* __restrict__ lncg, const float* __restrict__ lncb) {
    int j = blockIdx.x;
    bool ish = j < Hdim;
    int r = ish ? j : j - Hdim;
    const float4* Wr = (const float4*)((ish ? wh : wc) + (size_t)r * Hdim);
    const float4* X  = (const float4*)g_s.feat;
    float4 a = __ldcs(&Wr[threadIdx.x]), v = X[threadIdx.x];
    float s = a.x * v.x + a.y * v.y + a.z * v.z + a.w * v.w;
    s = block_sum(s);
    __shared__ bool lastb;
    if (threadIdx.x == 0) {
        float val = fmaxf(s + (ish ? bh[r] : bc[r]), 0.f);
        if (ish) g_s.tmph[r] = val; else g_s.tmpc[r] = val;
        __threadfence();
        lastb = (atomicAdd(&g_s.ticket1, 1u) == 2u * Hdim - 1u);
    }
    __syncthreads();
    if (!lastb) return;
    ln256(g_s.tmph, lnhg, lnhb, nullptr, g_s.h);
    ln256(g_s.tmpc, lncg, lncb, nullptr, g_s.c);
    if (threadIdx.x == 0) g_s.ticket1 = 0;
}

// ---------- LSTM cell (block j = hidden row j; warps 0-3: W_ih gates, 4-7: W_hh) ----------
// FUSELN: blocks Hdim/Hdim+1 do the LayerNorms for the next step.
template <bool FUSELN>
__global__ void __launch_bounds__(256) k_cell(
    const float* __restrict__ x, const float* __restrict__ hin, const float* __restrict__ cin,
    const float* __restrict__ wih, const float* __restrict__ whh,
    const float* __restrict__ bih, const float* __restrict__ bhh,
    float* __restrict__ hout, float* __restrict__ cout,
    const float* __restrict__ lnhg, const float* __restrict__ lnhb,
    const float* __restrict__ lncg, const float* __restrict__ lncb) {
    if (FUSELN && blockIdx.x >= Hdim) {
        bool ish = (blockIdx.x == Hdim);
        ln256(ish ? g_s.h1 : g_s.c1,
              ish ? lnhg : lncg, ish ? lnhb : lncb,
              ish ? g_s.h : g_s.c,
              ish ? g_s.tmph : g_s.tmpc);
        return;
    }
    int j = blockIdx.x;
    int w = threadIdx.x >> 5, lane = threadIdx.x & 31;
    const float* Wm  = (w < 4) ? wih : whh;
    const float* vec = (w < 4) ? x : hin;
    int row = j + (w & 3) * Hdim;
    const float4* Wr = (const float4*)(Wm + (size_t)row * Hdim);
    const float4* v4 = (const float4*)vec;
    float s = 0.f;
#pragma unroll
    for (int i = 0; i < 8; i++) {
        float4 a = Wr[lane + 32 * i];
        float4 b = v4[lane + 32 * i];
        s += a.x * b.x + a.y * b.y + a.z * b.z + a.w * b.w;
    }
    s = warp_sum(s);
    __shared__ float red[8];
    if (lane == 0) red[w] = s;
    __syncthreads();
    if (threadIdx.x == 0) {
        float gi = red[0] + red[4] + bih[j]            + bhh[j];
        float gf = red[1] + red[5] + bih[j + Hdim]     + bhh[j + Hdim];
        float gg = red[2] + red[6] + bih[j + 2 * Hdim] + bhh[j + 2 * Hdim];
        float go = red[3] + red[7] + bih[j + 3 * Hdim] + bhh[j + 3 * Hdim];
        float cn = sigf(gf) * cin[j] + sigf(gi) * tanhf(gg);
        cout[j] = cn;
        hout[j] = sigf(go) * tanhf(cn);
    }
}

// ---------- vocab GEMV (bf16) + interval bound + (last block) exact refine & emit ----------
__global__ void __launch_bounds__(256) k_fcb(
    const float* __restrict__ x, const float* __restrict__ fcb,
    const float* __restrict__ fcw32, const float* __restrict__ embed,
    const float* __restrict__ tot, float* __restrict__ out, int t) {
    int tid = threadIdx.x, wid = tid >> 5, lane = tid & 31;
    const float4* X = (const float4*)x;
    float4 xc[8];
#pragma unroll
    for (int k = 0; k < 4; k++) {
        int q = lane + 32 * k;
        xc[2 * k]     = X[2 * q];
        xc[2 * k + 1] = X[2 * q + 1];
    }
    unsigned long long wbest = 0ull;
    int r0 = (blockIdx.x * 8 + wid) * 4;
#pragma unroll
    for (int rr = 0; rr < 4; rr++) {
        int r = r0 + rr;
        const uint4* W = (const uint4*)(g_fcw + (size_t)r * (Hdim / 2));
        float v = 0.f, a = 0.f;
#pragma unroll
        for (int k = 0; k < 4; k++) {
            uint4 w4 = W[lane + 32 * k];
            float4 xA = xc[2 * k], xB = xc[2 * k + 1];
            float p0 = __uint_as_float(w4.x << 16)         * xA.x;
            float p1 = __uint_as_float(w4.x & 0xffff0000u) * xA.y;
            float p2 = __uint_as_float(w4.y << 16)         * xA.z;
            float p3 = __uint_as_float(w4.y & 0xffff0000u) * xA.w;
            float p4 = __uint_as_float(w4.z << 16)         * xB.x;
            float p5 = __uint_as_float(w4.z & 0xffff0000u) * xB.y;
            float p6 = __uint_as_float(w4.w << 16)         * xB.z;
            float p7 = __uint_as_float(w4.w & 0xffff0000u) * xB.w;
            v += p0 + p1 + p2 + p3 + p4 + p5 + p6 + p7;
            a += fabsf(p0) + fabsf(p1) + fabsf(p2) + fabsf(p3)
               + fabsf(p4) + fabsf(p5) + fabsf(p6) + fabsf(p7);
        }
        v = warp_sum(v);
        a = warp_sum(a);
        if (lane == 0) {
            v += fcb[r];
            float err = a * 0.0042f + 1e-6f;
            g_s.hi[r] = v + err;
            unsigned long long key = packkey(v - err, (unsigned)r);
            if (key > wbest) wbest = key;
        }
    }
    __shared__ unsigned long long sb[8];
    __shared__ bool lastb;
    if (lane == 0) sb[wid] = wbest;
    __syncthreads();
    if (tid == 0) {
        unsigned long long m = sb[0];
#pragma unroll
        for (int k = 1; k < 8; k++) if (sb[k] > m) m = sb[k];
        atomicMax(&g_s.lomax, m);
        __threadfence();
        lastb = (atomicAdd(&g_s.ticket2, 1u) == gridDim.x - 1u);
    }
    __syncthreads();
    if (!lastb) return;

    // ------- finish (sole surviving block; all hi/lomax writes fenced-visible) -------
    // Phase 1: pipelined strided scan -> candidate buffer (no collectives in load loop).
    // Phase 2: warp-parallel exact fp32 re-dots. Phase 3: ballot fallback (never taken).
    __shared__ int cand[1024];
    __shared__ int cnt;
    __shared__ unsigned long long swr[8];
    __shared__ int s_idx;
    __shared__ float s_tok;
    if (tid == 0) cnt = 0;
    __syncthreads();
    float lo = key_val(g_s.lomax);
    for (int r = tid; r < Vdim; r += 256)
        if (g_s.hi[r] >= lo) {
            int p = atomicAdd(&cnt, 1);
            if (p < 1024) cand[p] = r;
        }
    __syncthreads();
    int n = cnt < 1024 ? cnt : 1024;
    float4 x4c[8];
#pragma unroll
    for (int k = 0; k < 8; k++) x4c[k] = X[lane + 32 * k];
    unsigned long long rbest = 0ull;
    for (int ci = wid; ci < n; ci += 8) {
        int row = cand[ci];
        const float4* Wr = (const float4*)(fcw32 + (size_t)row * Hdim);
        float d = 0.f;
#pragma unroll
        for (int k = 0; k < 8; k++) {
            float4 a = Wr[lane + 32 * k];
            d += a.x * x4c[k].x + a.y * x4c[k].y + a.z * x4c[k].z + a.w * x4c[k].w;
        }
        d = warp_sum(d);
        if (lane == 0) {
            unsigned long long key = packkey(d + fcb[row], (unsigned)row);
            if (key > rbest) rbest = key;
        }
    }
    if (cnt > 1024) {   // pathological fallback: exact scan of every qualifying row
        for (int rb = wid * 32; rb < Vdim; rb += 256) {
            bool qual = (g_s.hi[rb + lane] >= lo);
            unsigned m = __ballot_sync(0xffffffffu, qual);
            while (m) {
                int b = __ffs(m) - 1;
                m &= m - 1;
                int row = rb + b;
                const float4* Wr = (const float4*)(fcw32 + (size_t)row * Hdim);
                float d = 0.f;
#pragma unroll
                for (int k = 0; k < 8; k++) {
                    float4 a = Wr[lane + 32 * k];
                    d += a.x * x4c[k].x + a.y * x4c[k].y + a.z * x4c[k].z + a.w * x4c[k].w;
                }
                d = warp_sum(d);
                if (lane == 0) {
                    unsigned long long key = packkey(d + fcb[row], (unsigned)row);
                    if (key > rbest) rbest = key;
                }
            }
        }
    }
    if (lane == 0) swr[wid] = rbest;
    __syncthreads();
    if (tid == 0) {
        unsigned long long m = swr[0];
#pragma unroll
        for (int k = 1; k < 8; k++) if (swr[k] > m) m = swr[k];
        s_idx = key_idx(m);
        s_tok = tot[s_idx];
        g_s.lomax = 0ull;
        g_s.ticket2 = 0u;
    }
    __syncthreads();
    int idx = s_idx;
    ((float4*)g_s.word)[tid] = ((const float4*)(embed + (size_t)idx * Hdim))[tid];
    out[tid * Tlen + t] = s_tok;   // batch == 256 == blockDim
}

extern "C" void kernel_launch(void* const* d_in, const int* in_sizes, int n_in,
                              void* d_out, int out_size) {
    const float* features  = (const float*)d_in[0];
    const float* fc1_w     = (const float*)d_in[1];
    const float* fc1_b     = (const float*)d_in[2];
    const float* init_h_w  = (const float*)d_in[3];
    const float* init_h_b  = (const float*)d_in[4];
    const float* init_c_w  = (const float*)d_in[5];
    const float* init_c_b  = (const float*)d_in[6];
    const float* ln_h_g    = (const float*)d_in[7];
    const float* ln_h_b    = (const float*)d_in[8];
    const float* ln_c_g    = (const float*)d_in[9];
    const float* ln_c_b    = (const float*)d_in[10];
    const float* w_ih1     = (const float*)d_in[11];
    const float* w_hh1     = (const float*)d_in[12];
    const float* b_ih1     = (const float*)d_in[13];
    const float* b_hh1     = (const float*)d_in[14];
    const float* w_ih2     = (const float*)d_in[15];
    const float* w_hh2     = (const float*)d_in[16];
    const float* b_ih2     = (const float*)d_in[17];
    const float* b_hh2     = (const float*)d_in[18];
    const float* fc_w      = (const float*)d_in[19];
    const float* fc_b      = (const float*)d_in[20];
    const float* embed_w   = (const float*)d_in[21];
    const float* totoken_w = (const float*)d_in[22];
    float* out = (float*)d_out;

    State* S = nullptr;
    cudaGetSymbolAddress((void**)&S, g_s);

    // prologue: feat GEMV + bf16 convert (one kernel), then init GEMVs + LN (one kernel)
    k_pro1<<<Hdim + 1480, 256>>>(features, fc1_w, fc1_b, fc_w);
    k_init2<<<2 * Hdim, 256>>>(init_h_w, init_h_b, init_c_w, init_c_b,
                               ln_h_g, ln_h_b, ln_c_g, ln_c_b);

    // ---- step 0 ----
    k_cell<false><<<Hdim, 256>>>(S->feat, S->h, S->c,
        w_ih1, w_hh1, b_ih1, b_hh1, S->h1, S->c1,
        nullptr, nullptr, nullptr, nullptr);
    k_cell<true><<<Hdim + 2, 256>>>(S->h1, S->h, S->c,
        w_ih2, w_hh2, b_ih2, b_hh2, S->h2[0], S->c2[0],
        ln_h_g, ln_h_b, ln_c_g, ln_c_b);
    k_cell<false><<<Hdim, 256>>>(S->h2[0], S->h, S->c,
        w_ih2, w_hh2, b_ih2, b_hh2, S->h3[0], S->c3[0],
        nullptr, nullptr, nullptr, nullptr);
    k_fcb<<<Vdim / 32, 256>>>(S->h3[0], fc_b, fc_w, embed_w, totoken_w, out, 0);

    // ---- steps 1..14 ----
    int p = 0;
    for (int t = 1; t < Tlen; t++) {
        int q = 1 - p;
        k_cell<false><<<Hdim, 256>>>(S->word, S->tmph, S->tmpc,
            w_ih1, w_hh1, b_ih1, b_hh1, S->h1, S->c1,
            nullptr, nullptr, nullptr, nullptr);
        k_cell<true><<<Hdim + 2, 256>>>(S->h1, S->h2[p], S->c2[p],
            w_ih2, w_hh2, b_ih2, b_hh2, S->h2[q], S->c2[q],
            ln_h_g, ln_h_b, ln_c_g, ln_c_b);
        k_cell<false><<<Hdim, 256>>>(S->h2[q], S->h3[p], S->c3[p],
            w_ih2, w_hh2, b_ih2, b_hh2, S->h3[q], S->c3[q],
            nullptr, nullptr, nullptr, nullptr);
        k_fcb<<<Vdim / 32, 256>>>(S->h3[q], fc_b, fc_w, embed_w, totoken_w, out, t);
        p = q;
    }
}

// round 7
// speedup vs baseline: 2.0525x; 1.5493x over previous
#include <cuda_runtime.h>
#include <cuda_bf16.h>
#include <cstdint>
#include <cstddef>

#define Hdim 1024
#define Edim 18432
#define Vdim 32000
#define Tlen 15

struct State {
    float feat[Hdim];
    float h[Hdim], c[Hdim];
    float tmph[Hdim], tmpc[Hdim];
    float h1[Hdim], c1[Hdim];
    float h2[2][Hdim], c2[2][Hdim];
    float h3[2][Hdim], c3[2][Hdim];
    float word[Hdim];
    float hi[Vdim];
    unsigned long long lomax, exmax;
    unsigned ticket1, ticket3;
};
__device__ State g_s;
__device__ unsigned g_fcw8[(size_t)Vdim * (Hdim / 4)];  // int8-packed fc_w (32.8 MB)
__device__ float g_scale[Vdim];                          // per-row quant scale
__device__ float g_sumw[Vdim];                           // per-row sum|w|

// ---------- helpers ----------
__device__ __forceinline__ float sigf(float x) { return 1.0f / (1.0f + expf(-x)); }

__device__ __forceinline__ float warp_sum(float s) {
#pragma unroll
    for (int o = 16; o; o >>= 1) s += __shfl_xor_sync(0xffffffffu, s, o);
    return s;
}
__device__ __forceinline__ int warp_isum(int s) {
#pragma unroll
    for (int o = 16; o; o >>= 1) s += __shfl_xor_sync(0xffffffffu, s, o);
    return s;
}
__device__ __forceinline__ float warp_max(float s) {
#pragma unroll
    for (int o = 16; o; o >>= 1) s = fmaxf(s, __shfl_xor_sync(0xffffffffu, s, o));
    return s;
}

// block reduce across 256 threads (8 warps)
__device__ __forceinline__ float block_sum(float s) {
    __shared__ float sm[8];
    __shared__ float outv;
    int w = threadIdx.x >> 5, lane = threadIdx.x & 31;
    s = warp_sum(s);
    if (lane == 0) sm[w] = s;
    __syncthreads();
    if (w == 0) {
        float r = (lane < 8) ? sm[lane] : 0.0f;
        r = warp_sum(r);
        if (lane == 0) outv = r;
    }
    __syncthreads();
    float res = outv;
    __syncthreads();
    return res;
}

__device__ __forceinline__ unsigned long long packkey(float v, unsigned idx) {
    unsigned u = __float_as_uint(v);
    u = (u & 0x80000000u) ? ~u : (u | 0x80000000u);
    return ((unsigned long long)u << 32) | (unsigned long long)(0xFFFFFFFFu - idx);
}
__device__ __forceinline__ float key_val(unsigned long long k) {
    unsigned u = (unsigned)(k >> 32);
    u = (u & 0x80000000u) ? (u ^ 0x80000000u) : ~u;
    return __uint_as_float(u);
}
__device__ __forceinline__ int key_idx(unsigned long long k) {
    return (int)(0xFFFFFFFFu - (unsigned)(k & 0xFFFFFFFFull));
}

__device__ __forceinline__ int clamp127(int q) {
    return q < -127 ? -127 : (q > 127 ? 127 : q);
}
__device__ __forceinline__ unsigned pack4(float4 f, float inv) {
    int a = clamp127(__float2int_rn(f.x * inv));
    int b = clamp127(__float2int_rn(f.y * inv));
    int c = clamp127(__float2int_rn(f.z * inv));
    int d = clamp127(__float2int_rn(f.w * inv));
    return (a & 0xFF) | ((b & 0xFF) << 8) | ((c & 0xFF) << 16) | ((d & 0xFF) << 24);
}

// ---------- LayerNorm by one 256-thread block ----------
__device__ void ln256(const float* __restrict__ x, const float* __restrict__ g,
                      const float* __restrict__ b, const float* __restrict__ base,
                      float* __restrict__ o) {
    float xv[4];
    float s = 0.f;
#pragma unroll
    for (int k = 0; k < 4; k++) { xv[k] = x[threadIdx.x + 256 * k]; s += xv[k]; }
    float m = block_sum(s) * (1.f / Hdim);
    float q = 0.f;
#pragma unroll
    for (int k = 0; k < 4; k++) { float d = xv[k] - m; q += d * d; }
    float v = block_sum(q) * (1.f / Hdim);
    float inv = rsqrtf(v + 1e-5f);
#pragma unroll
    for (int k = 0; k < 4; k++) {
        int i = threadIdx.x + 256 * k;
        float r = (xv[k] - m) * inv * g[i] + b[i];
        if (base) r += base[i];
        o[i] = r;
    }
}

// ---------- prologue: fc1 rows (blocks < Hdim) + int8 quantize fc_w (rest) ----------
__global__ void __launch_bounds__(256) k_pro1(
    const float* __restrict__ feats, const float* __restrict__ w,
    const float* __restrict__ bias, const float* __restrict__ fcw32) {
    int wid = threadIdx.x >> 5, lane = threadIdx.x & 31;
    if (blockIdx.x < Hdim) {
        int j = blockIdx.x;
        const float4* Wr = (const float4*)(w + (size_t)j * Edim);
        const float4* X  = (const float4*)feats;
        float s = 0.f;
        for (int i = threadIdx.x; i < Edim / 4; i += 256) {
            float4 a = __ldcs(&Wr[i]), v = X[i];
            s += a.x * v.x + a.y * v.y + a.z * v.z + a.w * v.w;
        }
        s = block_sum(s);
        if (threadIdx.x == 0) g_s.feat[j] = fmaxf(s + bias[j], 0.f);
    } else {
        // one warp per vocab row: read 1024 floats, stats, quantize to int8
        int r = (blockIdx.x - Hdim) * 8 + wid;
        const float4* Wr = (const float4*)(fcw32 + (size_t)r * Hdim);
        float4 v[8];
        float ma = 0.f, sa = 0.f;
#pragma unroll
        for (int k = 0; k < 8; k++) {
            v[k] = __ldcs(&Wr[lane + 32 * k]);
            ma = fmaxf(ma, fmaxf(fmaxf(fabsf(v[k].x), fabsf(v[k].y)),
                                 fmaxf(fabsf(v[k].z), fabsf(v[k].w))));
            sa += fabsf(v[k].x) + fabsf(v[k].y) + fabsf(v[k].z) + fabsf(v[k].w);
        }
        ma = warp_max(ma);
        sa = warp_sum(sa);
        float mg = fmaxf(ma, 1e-30f);
        float s = mg * (1.f / 127.f);
        float inv = 127.f / mg;
        unsigned* W8 = g_fcw8 + (size_t)r * (Hdim / 4);
#pragma unroll
        for (int k = 0; k < 8; k++) W8[lane + 32 * k] = pack4(v[k], inv);
        if (lane == 0) { g_scale[r] = s; g_sumw[r] = sa; }
    }
}

// ---------- init h/c GEMVs + (last block) prologue LayerNorms ----------
__global__ void __launch_bounds__(256) k_init2(
    const float* __restrict__ wh, const float* __restrict__ bh,
    const float* __restrict__ wc, const float* __restrict__ bc,
    const float* __restrict__ lnhg, const float* __restrict__ lnhb,
    const float* __restrict__ lncg, const float* __restrict__ lncb) {
    int j = blockIdx.x;
    bool ish = j < Hdim;
    int r = ish ? j : j - Hdim;
    const float4* Wr = (const float4*)((ish ? wh : wc) + (size_t)r * Hdim);
    const float4* X  = (const float4*)g_s.feat;
    float4 a = __ldcs(&Wr[threadIdx.x]), v = X[threadIdx.x];
    float s = a.x * v.x + a.y * v.y + a.z * v.z + a.w * v.w;
    s = block_sum(s);
    __shared__ bool lastb;
    if (threadIdx.x == 0) {
        float val = fmaxf(s + (ish ? bh[r] : bc[r]), 0.f);
        if (ish) g_s.tmph[r] = val; else g_s.tmpc[r] = val;
        __threadfence();
        lastb = (atomicAdd(&g_s.ticket1, 1u) == 2u * Hdim - 1u);
    }
    __syncthreads();
    if (!lastb) return;
    ln256(g_s.tmph, lnhg, lnhb, nullptr, g_s.h);
    ln256(g_s.tmpc, lncg, lncb, nullptr, g_s.c);
    if (threadIdx.x == 0) g_s.ticket1 = 0;
}

// ---------- LSTM cell (block j = hidden row j; warps 0-3: W_ih gates, 4-7: W_hh) ----------
template <bool FUSELN>
__global__ void __launch_bounds__(256) k_cell(
    const float* __restrict__ x, const float* __restrict__ hin, const float* __restrict__ cin,
    const float* __restrict__ wih, const float* __restrict__ whh,
    const float* __restrict__ bih, const float* __restrict__ bhh,
    float* __restrict__ hout, float* __restrict__ cout,
    const float* __restrict__ lnhg, const float* __restrict__ lnhb,
    const float* __restrict__ lncg, const float* __restrict__ lncb) {
    if (FUSELN && blockIdx.x >= Hdim) {
        bool ish = (blockIdx.x == Hdim);
        ln256(ish ? g_s.h1 : g_s.c1,
              ish ? lnhg : lncg, ish ? lnhb : lncb,
              ish ? g_s.h : g_s.c,
              ish ? g_s.tmph : g_s.tmpc);
        return;
    }
    int j = blockIdx.x;
    int w = threadIdx.x >> 5, lane = threadIdx.x & 31;
    const float* Wm  = (w < 4) ? wih : whh;
    const float* vec = (w < 4) ? x : hin;
    int row = j + (w & 3) * Hdim;
    const float4* Wr = (const float4*)(Wm + (size_t)row * Hdim);
    const float4* v4 = (const float4*)vec;
    float s = 0.f;
#pragma unroll
    for (int i = 0; i < 8; i++) {
        float4 a = Wr[lane + 32 * i];
        float4 b = v4[lane + 32 * i];
        s += a.x * b.x + a.y * b.y + a.z * b.z + a.w * b.w;
    }
    s = warp_sum(s);
    __shared__ float red[8];
    if (lane == 0) red[w] = s;
    __syncthreads();
    if (threadIdx.x == 0) {
        float gi = red[0] + red[4] + bih[j]            + bhh[j];
        float gf = red[1] + red[5] + bih[j + Hdim]     + bhh[j + Hdim];
        float gg = red[2] + red[6] + bih[j + 2 * Hdim] + bhh[j + 2 * Hdim];
        float go = red[3] + red[7] + bih[j + 3 * Hdim] + bhh[j + 3 * Hdim];
        float cn = sigf(gf) * cin[j] + sigf(gi) * tanhf(gg);
        cout[j] = cn;
        hout[j] = sigf(go) * tanhf(cn);
    }
}

// ---------- vocab GEMV in int8 (dp4a, exact int accum) + interval bound ----------
__global__ void __launch_bounds__(256) k_fcb8(
    const float* __restrict__ x, const float* __restrict__ fcb) {
    int wid = threadIdx.x >> 5, lane = threadIdx.x & 31;
    const float4* X = (const float4*)x;
    float4 xv[8];
    float ma = 0.f, sa = 0.f;
#pragma unroll
    for (int k = 0; k < 8; k++) {
        xv[k] = X[lane + 32 * k];
        ma = fmaxf(ma, fmaxf(fmaxf(fabsf(xv[k].x), fabsf(xv[k].y)),
                             fmaxf(fabsf(xv[k].z), fabsf(xv[k].w))));
        sa += fabsf(xv[k].x) + fabsf(xv[k].y) + fabsf(xv[k].z) + fabsf(xv[k].w);
    }
    ma = warp_max(ma);
    float sumAbsX = warp_sum(sa);
    float mg = fmaxf(ma, 1e-30f);
    float sx = mg * (1.f / 127.f);
    float invx = 127.f / mg;
    unsigned qx[8];
#pragma unroll
    for (int k = 0; k < 8; k++) qx[k] = pack4(xv[k], invx);

    unsigned long long wbest = 0ull;
    int r0 = (blockIdx.x * 8 + wid) * 4;
#pragma unroll
    for (int rr = 0; rr < 4; rr++) {
        int r = r0 + rr;
        const unsigned* W8 = g_fcw8 + (size_t)r * (Hdim / 4);
        int acc = 0;
#pragma unroll
        for (int k = 0; k < 8; k++)
            acc = __dp4a((int)W8[lane + 32 * k], (int)qx[k], acc);
        acc = warp_isum(acc);
        if (lane == 0) {
            float sr = g_scale[r];
            float v = sr * sx * (float)acc + fcb[r];
            // |true - quant| <= 0.5*sx*Sum|w| + 0.5*sr*(Sum|x| + (H/2)*sx); inflate for fp32 slop
            float err = (0.5f * sx * g_sumw[r] + 0.5f * sr * (sumAbsX + 512.f * sx)) * 1.1f
                        + 1e-7f;
            g_s.hi[r] = v + err;
            unsigned long long key = packkey(v - err, (unsigned)r);
            if (key > wbest) wbest = key;
        }
    }
    __shared__ unsigned long long sb[8];
    if (lane == 0) sb[wid] = wbest;
    __syncthreads();
    if (threadIdx.x == 0) {
        unsigned long long m = sb[0];
#pragma unroll
        for (int k = 1; k < 8; k++) if (sb[k] > m) m = sb[k];
        atomicMax(&g_s.lomax, m);
    }
}

// ---------- refine: exact fp32 re-dot of candidates, global argmax, emit ----------
// grid = Vdim/256 = 125 blocks; each thread owns exactly one vocab row.
__global__ void __launch_bounds__(256) k_refine(
    const float* __restrict__ x, const float* __restrict__ fcw32,
    const float* __restrict__ fcb, const float* __restrict__ embed,
    const float* __restrict__ tot, float* __restrict__ out, int t) {
    int tid = threadIdx.x, wid = tid >> 5, lane = tid & 31;
    __shared__ int cand[256];
    __shared__ int cnt;
    __shared__ unsigned long long swr[8];
    __shared__ bool lastb;
    __shared__ int s_idx;
    __shared__ float s_tok;
    if (tid == 0) cnt = 0;
    __syncthreads();
    float lo = key_val(g_s.lomax);
    int r = blockIdx.x * 256 + tid;
    if (g_s.hi[r] >= lo) cand[atomicAdd(&cnt, 1)] = r;   // <=256 by construction
    __syncthreads();

    const float4* X = (const float4*)x;
    float4 x4c[8];
#pragma unroll
    for (int k = 0; k < 8; k++) x4c[k] = X[lane + 32 * k];
    unsigned long long rbest = 0ull;
    int n = cnt;
    for (int ci = wid; ci < n; ci += 8) {
        int row = cand[ci];
        const float4* Wr = (const float4*)(fcw32 + (size_t)row * Hdim);
        float d = 0.f;
#pragma unroll
        for (int k = 0; k < 8; k++) {
            float4 a = Wr[lane + 32 * k];
            d += a.x * x4c[k].x + a.y * x4c[k].y + a.z * x4c[k].z + a.w * x4c[k].w;
        }
        d = warp_sum(d);
        if (lane == 0) {
            unsigned long long key = packkey(d + fcb[row], (unsigned)row);
            if (key > rbest) rbest = key;
        }
    }
    if (lane == 0) swr[wid] = rbest;
    __syncthreads();
    if (tid == 0) {
        unsigned long long m = swr[0];
#pragma unroll
        for (int k = 1; k < 8; k++) if (swr[k] > m) m = swr[k];
        if (m) atomicMax(&g_s.exmax, m);
        __threadfence();
        lastb = (atomicAdd(&g_s.ticket3, 1u) == gridDim.x - 1u);
    }
    __syncthreads();
    if (!lastb) return;

    if (tid == 0) {
        unsigned long long m = atomicAdd(&g_s.exmax, 0ull);
        s_idx = key_idx(m);
        s_tok = tot[s_idx];
        g_s.lomax = 0ull;
        g_s.exmax = 0ull;
        g_s.ticket3 = 0u;
    }
    __syncthreads();
    int idx = s_idx;
    ((float4*)g_s.word)[tid] = ((const float4*)(embed + (size_t)idx * Hdim))[tid];
    out[tid * Tlen + t] = s_tok;   // batch == 256 == blockDim
}

extern "C" void kernel_launch(void* const* d_in, const int* in_sizes, int n_in,
                              void* d_out, int out_size) {
    const float* features  = (const float*)d_in[0];
    const float* fc1_w     = (const float*)d_in[1];
    const float* fc1_b     = (const float*)d_in[2];
    const float* init_h_w  = (const float*)d_in[3];
    const float* init_h_b  = (const float*)d_in[4];
    const float* init_c_w  = (const float*)d_in[5];
    const float* init_c_b  = (const float*)d_in[6];
    const float* ln_h_g    = (const float*)d_in[7];
    const float* ln_h_b    = (const float*)d_in[8];
    const float* ln_c_g    = (const float*)d_in[9];
    const float* ln_c_b    = (const float*)d_in[10];
    const float* w_ih1     = (const float*)d_in[11];
    const float* w_hh1     = (const float*)d_in[12];
    const float* b_ih1     = (const float*)d_in[13];
    const float* b_hh1     = (const float*)d_in[14];
    const float* w_ih2     = (const float*)d_in[15];
    const float* w_hh2     = (const float*)d_in[16];
    const float* b_ih2     = (const float*)d_in[17];
    const float* b_hh2     = (const float*)d_in[18];
    const float* fc_w      = (const float*)d_in[19];
    const float* fc_b      = (const float*)d_in[20];
    const float* embed_w   = (const float*)d_in[21];
    const float* totoken_w = (const float*)d_in[22];
    float* out = (float*)d_out;

    State* S = nullptr;
    cudaGetSymbolAddress((void**)&S, g_s);

    // prologue: fc1 GEMV + int8 quantization of fc_w, then init GEMVs + LN
    k_pro1<<<Hdim + Vdim / 8, 256>>>(features, fc1_w, fc1_b, fc_w);
    k_init2<<<2 * Hdim, 256>>>(init_h_w, init_h_b, init_c_w, init_c_b,
                               ln_h_g, ln_h_b, ln_c_g, ln_c_b);

    // ---- step 0 ----
    k_cell<false><<<Hdim, 256>>>(S->feat, S->h, S->c,
        w_ih1, w_hh1, b_ih1, b_hh1, S->h1, S->c1,
        nullptr, nullptr, nullptr, nullptr);
    k_cell<true><<<Hdim + 2, 256>>>(S->h1, S->h, S->c,
        w_ih2, w_hh2, b_ih2, b_hh2, S->h2[0], S->c2[0],
        ln_h_g, ln_h_b, ln_c_g, ln_c_b);
    k_cell<false><<<Hdim, 256>>>(S->h2[0], S->h, S->c,
        w_ih2, w_hh2, b_ih2, b_hh2, S->h3[0], S->c3[0],
        nullptr, nullptr, nullptr, nullptr);
    k_fcb8<<<Vdim / 32, 256>>>(S->h3[0], fc_b);
    k_refine<<<Vdim / 256, 256>>>(S->h3[0], fc_w, fc_b, embed_w, totoken_w, out, 0);

    // ---- steps 1..14 ----
    int p = 0;
    for (int t = 1; t < Tlen; t++) {
        int q = 1 - p;
        k_cell<false><<<Hdim, 256>>>(S->word, S->tmph, S->tmpc,
            w_ih1, w_hh1, b_ih1, b_hh1, S->h1, S->c1,
            nullptr, nullptr, nullptr, nullptr);
        k_cell<true><<<Hdim + 2, 256>>>(S->h1, S->h2[p], S->c2[p],
            w_ih2, w_hh2, b_ih2, b_hh2, S->h2[q], S->c2[q],
            ln_h_g, ln_h_b, ln_c_g, ln_c_b);
        k_cell<false><<<Hdim, 256>>>(S->h2[q], S->h3[p], S->c3[p],
            w_ih2, w_hh2, b_ih2, b_hh2, S->h3[q], S->c3[q],
            nullptr, nullptr, nullptr, nullptr);
        k_fcb8<<<Vdim / 32, 256>>>(S->h3[q], fc_b);
        k_refine<<<Vdim / 256, 256>>>(S->h3[q], fc_w, fc_b, embed_w, totoken_w, out, t);
        p = q;
    }
}